// round 10
// baseline (speedup 1.0000x reference)
#include <cuda_runtime.h>
#include <cstdint>

// ---------------- problem constants ----------------
#define B_   32
#define H_   168
#define N_   512
#define F_   8
#define P_   24
#define KIN_ (N_ * F_)   // 4096
#define G4N_ (4 * N_)    // 2048
#define MR_  (B_ * H_)   // 5376
#define RGRID 128        // recurrence grid (all co-resident; 128 <= 148 SMs)
#define HS_  516         // hsh row stride (conflict-free A-frag loads)
#define PS_  36          // psum b-stride (conflict-free partial STS/LDS)

typedef unsigned long long ull;

// ---------------- device scratch (no runtime allocation allowed) ----------------
__device__ float d_xr[(size_t)MR_ * N_];        // 11 MB
__device__ float d_xk[(size_t)MR_ * G4N_];      // 44 MB (includes lstm_b)
__device__ float d_wdec[(size_t)N_ * G4N_];     // 4 MB  (lstm_k + lstm_rk)
__device__ float d_h[2][B_ * N_];               // h[b][n], double buffered
__device__ float d_preds[(size_t)B_ * P_ * N_]; // 1.5 MB
__device__ ull g_arrive64;                      // monotonic barrier counter

// ---------------- tf32 helpers ----------------
__device__ __forceinline__ unsigned f2tf(float x) {
    unsigned r;
    asm("cvt.rna.tf32.f32 %0, %1;" : "=r"(r) : "f"(x));
    return r;
}

__device__ __forceinline__ void mma_tf32(float* c, const unsigned* a,
                                         unsigned b0, unsigned b1) {
    asm volatile(
        "mma.sync.aligned.m16n8k8.row.col.f32.tf32.tf32.f32 "
        "{%0,%1,%2,%3},{%4,%5,%6,%7},{%8,%9},{%0,%1,%2,%3};"
        : "+f"(c[0]), "+f"(c[1]), "+f"(c[2]), "+f"(c[3])
        : "r"(a[0]), "r"(a[1]), "r"(a[2]), "r"(a[3]), "r"(b0), "r"(b1));
}

// ======================================================================
// C[M,N] = A[M,K] @ B[K,N] + bias[N], tf32 mma.
// Block tile 64x64 (higher occupancy: ~3 blocks/SM, 6 warps/SMSP),
// 8 warps (2x4), warp tile 32x16, K-tile 32, reg-double-buffered.
// ======================================================================
#define BM 64
#define BN 64
#define BKt 32

__global__ __launch_bounds__(256) void gemm_tf32(
    const float* __restrict__ A, const float* __restrict__ Bw,
    const float* __restrict__ bias, float* __restrict__ C,
    int M, int N, int K)
{
    __shared__ float As[2][BM][BKt + 4];   // 64 x 36
    __shared__ float Bs[2][BKt][BN + 4];   // 32 x 68

    const int tid  = threadIdx.x;
    const int lane = tid & 31;
    const int warp = tid >> 5;
    const int wm = warp >> 2;   // 0..1 (M)
    const int wn = warp & 3;    // 0..3 (N)
    const int bm = blockIdx.y, bn = blockIdx.x;
    const int g  = lane >> 2;
    const int tg = lane & 3;

    const float* Ag = A + (size_t)bm * BM * K;
    const float* Bg = Bw + (size_t)bn * BN;

    int arow[2], akc[2], brow[2], bnc[2];
#pragma unroll
    for (int i = 0; i < 2; i++) {
        int f4 = tid + i * 256;
        arow[i] = f4 >> 3;           // 8 f4 per A row
        akc[i]  = (f4 & 7) << 2;
        brow[i] = f4 >> 4;           // 16 f4 per B row
        bnc[i]  = (f4 & 15) << 2;
    }

    float acc[2][2][4];
#pragma unroll
    for (int i = 0; i < 2; i++)
#pragma unroll
        for (int j = 0; j < 2; j++)
#pragma unroll
            for (int r = 0; r < 4; r++) acc[i][j][r] = 0.f;

    float4 ra[2], rb[2];
#pragma unroll
    for (int i = 0; i < 2; i++) {
        ra[i] = *(const float4*)(Ag + (size_t)arow[i] * K + akc[i]);
        rb[i] = *(const float4*)(Bg + (size_t)brow[i] * N + bnc[i]);
    }

    const int T = K / BKt;
    int buf = 0;
#pragma unroll
    for (int i = 0; i < 2; i++) {
        As[0][arow[i]][akc[i] + 0] = __uint_as_float(f2tf(ra[i].x));
        As[0][arow[i]][akc[i] + 1] = __uint_as_float(f2tf(ra[i].y));
        As[0][arow[i]][akc[i] + 2] = __uint_as_float(f2tf(ra[i].z));
        As[0][arow[i]][akc[i] + 3] = __uint_as_float(f2tf(ra[i].w));
        Bs[0][brow[i]][bnc[i] + 0] = __uint_as_float(f2tf(rb[i].x));
        Bs[0][brow[i]][bnc[i] + 1] = __uint_as_float(f2tf(rb[i].y));
        Bs[0][brow[i]][bnc[i] + 2] = __uint_as_float(f2tf(rb[i].z));
        Bs[0][brow[i]][bnc[i] + 3] = __uint_as_float(f2tf(rb[i].w));
    }
    __syncthreads();

    for (int t = 0; t < T; t++) {
        if (t + 1 < T) {
            const int kt = (t + 1) * BKt;
#pragma unroll
            for (int i = 0; i < 2; i++) {
                ra[i] = *(const float4*)(Ag + (size_t)arow[i] * K + kt + akc[i]);
                rb[i] = *(const float4*)(Bg + (size_t)(kt + brow[i]) * N + bnc[i]);
            }
        }

#pragma unroll
        for (int ks = 0; ks < 4; ks++) {
            const int k0 = ks * 8;
            unsigned a[2][4], b[2][2];
#pragma unroll
            for (int mi = 0; mi < 2; mi++) {
                int m0 = wm * 32 + mi * 16;
                a[mi][0] = __float_as_uint(As[buf][m0 + g    ][k0 + tg    ]);
                a[mi][1] = __float_as_uint(As[buf][m0 + g + 8][k0 + tg    ]);
                a[mi][2] = __float_as_uint(As[buf][m0 + g    ][k0 + tg + 4]);
                a[mi][3] = __float_as_uint(As[buf][m0 + g + 8][k0 + tg + 4]);
            }
#pragma unroll
            for (int ni = 0; ni < 2; ni++) {
                int n0 = wn * 16 + ni * 8;
                b[ni][0] = __float_as_uint(Bs[buf][k0 + tg    ][n0 + g]);
                b[ni][1] = __float_as_uint(Bs[buf][k0 + tg + 4][n0 + g]);
            }
#pragma unroll
            for (int mi = 0; mi < 2; mi++)
#pragma unroll
                for (int ni = 0; ni < 2; ni++)
                    mma_tf32(acc[mi][ni], a[mi], b[ni][0], b[ni][1]);
        }

        if (t + 1 < T) {
            const int nb = buf ^ 1;
#pragma unroll
            for (int i = 0; i < 2; i++) {
                As[nb][arow[i]][akc[i] + 0] = __uint_as_float(f2tf(ra[i].x));
                As[nb][arow[i]][akc[i] + 1] = __uint_as_float(f2tf(ra[i].y));
                As[nb][arow[i]][akc[i] + 2] = __uint_as_float(f2tf(ra[i].z));
                As[nb][arow[i]][akc[i] + 3] = __uint_as_float(f2tf(ra[i].w));
                Bs[nb][brow[i]][bnc[i] + 0] = __uint_as_float(f2tf(rb[i].x));
                Bs[nb][brow[i]][bnc[i] + 1] = __uint_as_float(f2tf(rb[i].y));
                Bs[nb][brow[i]][bnc[i] + 2] = __uint_as_float(f2tf(rb[i].z));
                Bs[nb][brow[i]][bnc[i] + 3] = __uint_as_float(f2tf(rb[i].w));
            }
            __syncthreads();
            buf = nb;
        }
    }

#pragma unroll
    for (int mi = 0; mi < 2; mi++) {
        int r0 = bm * BM + wm * 32 + mi * 16 + g;
#pragma unroll
        for (int ni = 0; ni < 2; ni++) {
            int c0 = bn * BN + wn * 16 + ni * 8 + tg * 2;
            float b0 = bias[c0], b1 = bias[c0 + 1];
            *(float2*)(C + (size_t)r0 * N + c0) =
                make_float2(acc[mi][ni][0] + b0, acc[mi][ni][1] + b1);
            *(float2*)(C + (size_t)(r0 + 8) * N + c0) =
                make_float2(acc[mi][ni][2] + b0, acc[mi][ni][3] + b1);
        }
    }
}

// ======================================================================
// Wdec = lstm_k + lstm_rk (elementwise, float4)
// ======================================================================
__global__ void add_w(const float* __restrict__ a, const float* __restrict__ b,
                      float* __restrict__ o, int n4)
{
    int i = blockIdx.x * blockDim.x + threadIdx.x;
    if (i < n4) {
        float4 x = ((const float4*)a)[i];
        float4 y = ((const float4*)b)[i];
        ((float4*)o)[i] = make_float4(x.x + y.x, x.y + y.y, x.z + y.z, x.w + y.w);
    }
}

// ======================================================================
// Persistent recurrence kernel (R10):
//  - B-frag HI values live permanently in REGISTERS (32/thread)
//  - B-frag LO values in smem, frag-major: 1 LDS.128 per f-iter (was 8 LDS.32)
//  - tight-spin single-counter barrier
// ======================================================================
__device__ __forceinline__ void grid_barrier()
{
    __syncthreads();
    if (threadIdx.x == 0) {
        ull my;
        asm volatile("atom.add.release.gpu.global.u64 %0, [%1], 1;"
                     : "=l"(my) : "l"(&g_arrive64) : "memory");
        ull target = (my / RGRID + 1ull) * RGRID;
        ull v;
        do {
            asm volatile("ld.acquire.gpu.global.u64 %0, [%1];"
                         : "=l"(v) : "l"(&g_arrive64) : "memory");
        } while (v < target);
    }
    __syncthreads();
}

__device__ __forceinline__ float sigf(float x) { return 1.f / (1.f + expf(-x)); }

// Fill per-thread B-frag hi registers from global W; mi==0 warps also store
// lo remainders frag-major into smem (1 uint4 slot per (kg,f,lane)).
__device__ __forceinline__ void fill_wfrag(const float* __restrict__ W, int nc0,
                                           int kg, int g, int tg, int lane, int mi,
                                           unsigned bh[8][4], unsigned* wLoF)
{
    const int cA = (g >> 2) * 512 + nc0 + (g & 3);        // slice col g
    const int cB = (2 + (g >> 2)) * 512 + nc0 + (g & 3);  // slice col 8+g
#pragma unroll
    for (int f = 0; f < 8; f++) {
        const int k0 = kg * 64 + f * 8;
        float w0 = W[(size_t)(k0 + tg    ) * G4N_ + cA];
        float w1 = W[(size_t)(k0 + tg + 4) * G4N_ + cA];
        float w2 = W[(size_t)(k0 + tg    ) * G4N_ + cB];
        float w3 = W[(size_t)(k0 + tg + 4) * G4N_ + cB];
        unsigned h0 = f2tf(w0), h1 = f2tf(w1), h2 = f2tf(w2), h3 = f2tf(w3);
        bh[f][0] = h0; bh[f][1] = h1; bh[f][2] = h2; bh[f][3] = h3;
        if (mi == 0) {
            uint4 lo;
            lo.x = __float_as_uint(w0 - __uint_as_float(h0));
            lo.y = __float_as_uint(w1 - __uint_as_float(h1));
            lo.z = __float_as_uint(w2 - __uint_as_float(h2));
            lo.w = __float_as_uint(w3 - __uint_as_float(h3));
            *(uint4*)&wLoF[((kg * 8 + f) * 32 + lane) * 4] = lo;
        }
    }
}

__global__ __launch_bounds__(512, 1) void recurrence(
    const float* __restrict__ Wenc,   // lstm_rk [512][2048]
    const float* __restrict__ Wdec,   // [512][2048]
    const float* __restrict__ xk,     // [B*H][2048] (bias folded in)
    const float* __restrict__ lb,     // lstm_b [2048]
    float* __restrict__ preds)        // [B][P][N]
{
    extern __shared__ float sm[];
    unsigned* wLoF = (unsigned*)sm;           // 8192 u32 (8 kg x 8 f x 32 lane x 4)
    float* hsh     = sm + 8192;               // 32 x 516 = 16512 floats
    float* psum    = sm + 24704;              // 8 x 16 x 36 = 4608 floats

    const int tid  = threadIdx.x;
    const int lane = tid & 31;
    const int warp = tid >> 5;
    const int g    = lane >> 2;
    const int tg   = lane & 3;
    const int kg   = warp & 7;     // k-split group (k in [kg*64, kg*64+64))
    const int mi   = warp >> 3;    // row half
    const int m0   = mi * 16;
    const int nc0  = blockIdx.x * 4;

    // ---- B-frag hi -> registers; lo -> smem (encoder W) ----
    unsigned bh[8][4];
    fill_wfrag(Wenc, nc0, kg, g, tg, lane, mi, bh, wLoF);

    // ---- init ----
    const int b  = tid & 31;
    const int cu = tid >> 5;
    float lbr[4], cst = 0.f, pf[4];
    if (tid < 128) {
        d_h[0][(size_t)b * N_ + nc0 + cu] = 0.f;
#pragma unroll
        for (int q = 0; q < 4; q++) lbr[q] = lb[q * 512 + nc0 + cu];
        const float* xp = xk + ((size_t)b * H_) * G4N_ + nc0 + cu;
        pf[0] = __ldg(xp);
        pf[1] = __ldg(xp + 512);
        pf[2] = __ldg(xp + 1024);
        pf[3] = __ldg(xp + 1536);
    }
    grid_barrier();

    for (int s = 0; s < H_ + P_; s++) {
        // enc -> dec transition: swap W frags (one time)
        if (s == H_) fill_wfrag(Wdec, nc0, kg, g, tg, lane, mi, bh, wLoF);

        // ---- stage h[b][n] -> hsh (stride 516), bypass L1 ----
        const float4* hg = (const float4*)d_h[s & 1];
#pragma unroll
        for (int i = 0; i < 8; i++) {
            int idx = tid + i * 512;       // idx = bb*128 + n4
            int bb = idx >> 7, n4 = idx & 127;
            float4 v = __ldcg(hg + idx);
            *(float4*)&hsh[bb * HS_ + n4 * 4] = v;
        }
        __syncthreads();

        // ---- tensor-core partial GEMM: rows [m0,m0+16), k-slice [kg*64,+64) ----
        float acc0[4] = {0.f, 0.f, 0.f, 0.f};
        float acc1[4] = {0.f, 0.f, 0.f, 0.f};
#pragma unroll
        for (int f = 0; f < 8; f++) {
            const int k0 = kg * 64 + f * 8;
            float a0 = hsh[(m0 + g    ) * HS_ + k0 + tg    ];
            float a1 = hsh[(m0 + g + 8) * HS_ + k0 + tg    ];
            float a2 = hsh[(m0 + g    ) * HS_ + k0 + tg + 4];
            float a3 = hsh[(m0 + g + 8) * HS_ + k0 + tg + 4];
            unsigned ahi[4], alo[4];
            ahi[0] = f2tf(a0); alo[0] = __float_as_uint(a0 - __uint_as_float(ahi[0]));
            ahi[1] = f2tf(a1); alo[1] = __float_as_uint(a1 - __uint_as_float(ahi[1]));
            ahi[2] = f2tf(a2); alo[2] = __float_as_uint(a2 - __uint_as_float(ahi[2]));
            ahi[3] = f2tf(a3); alo[3] = __float_as_uint(a3 - __uint_as_float(ahi[3]));
            uint4 lo4 = *(const uint4*)&wLoF[((kg * 8 + f) * 32 + lane) * 4];
            // 3-term compensated accumulate (hi from registers)
            mma_tf32(acc0, ahi, bh[f][0], bh[f][1]);
            mma_tf32(acc0, alo, bh[f][0], bh[f][1]);
            mma_tf32(acc0, ahi, lo4.x, lo4.y);
            mma_tf32(acc1, ahi, bh[f][2], bh[f][3]);
            mma_tf32(acc1, alo, bh[f][2], bh[f][3]);
            mma_tf32(acc1, ahi, lo4.z, lo4.w);
        }
        // ---- stash partials ----
        {
            const int c0 = tg * 2, r0 = m0 + g;
            psum[(kg * 16 + c0        ) * PS_ + r0    ] = acc0[0];
            psum[(kg * 16 + c0 + 1    ) * PS_ + r0    ] = acc0[1];
            psum[(kg * 16 + c0        ) * PS_ + r0 + 8] = acc0[2];
            psum[(kg * 16 + c0 + 1    ) * PS_ + r0 + 8] = acc0[3];
            psum[(kg * 16 + 8 + c0    ) * PS_ + r0    ] = acc1[0];
            psum[(kg * 16 + 8 + c0 + 1) * PS_ + r0    ] = acc1[1];
            psum[(kg * 16 + 8 + c0    ) * PS_ + r0 + 8] = acc1[2];
            psum[(kg * 16 + 8 + c0 + 1) * PS_ + r0 + 8] = acc1[3];
        }
        __syncthreads();

        // ---- cell update: thread (b, cu) handles hidden col nc0+cu ----
        if (tid < 128) {
            float pfn[4];
            if (s + 1 < H_) {
                const float* xp = xk + ((size_t)b * H_ + (s + 1)) * G4N_ + nc0 + cu;
                pfn[0] = __ldg(xp);
                pfn[1] = __ldg(xp + 512);
                pfn[2] = __ldg(xp + 1024);
                pfn[3] = __ldg(xp + 1536);
            } else {
                pfn[0] = lbr[0]; pfn[1] = lbr[1]; pfn[2] = lbr[2]; pfn[3] = lbr[3];
            }

            float z[4];
#pragma unroll
            for (int q = 0; q < 4; q++) {
                const int n = q * 4 + cu;
                float accv = pf[q];
#pragma unroll
                for (int kk = 0; kk < 8; kk++)
                    accv += psum[(kk * 16 + n) * PS_ + b];
                z[q] = accv;
            }
            float ii = sigf(z[0]), ff = sigf(z[1]);
            float gg = tanhf(z[2]), oo = sigf(z[3]);
            cst = ff * cst + ii * gg;
            float hn = oo * tanhf(cst);
            d_h[(s + 1) & 1][(size_t)b * N_ + nc0 + cu] = hn;
            if (s >= H_)
                preds[((size_t)b * P_ + (s - H_)) * N_ + nc0 + cu] = hn;

            pf[0] = pfn[0]; pf[1] = pfn[1]; pf[2] = pfn[2]; pf[3] = pfn[3];
        }
        grid_barrier();
    }
}

// ======================================================================
// launch
// ======================================================================
extern "C" void kernel_launch(void* const* d_in, const int* in_sizes, int n_in,
                              void* d_out, int out_size)
{
    const float* x       = (const float*)d_in[0];
    const float* conv_w  = (const float*)d_in[1];
    const float* conv_b  = (const float*)d_in[2];
    const float* lstm_k  = (const float*)d_in[3];
    const float* lstm_rk = (const float*)d_in[4];
    const float* lstm_b  = (const float*)d_in[5];
    const float* dense_w = (const float*)d_in[6];
    const float* dense_b = (const float*)d_in[7];
    float* out = (float*)d_out;

    float *xr, *xk, *wdec, *preds;
    cudaGetSymbolAddress((void**)&xr,    d_xr);
    cudaGetSymbolAddress((void**)&xk,    d_xk);
    cudaGetSymbolAddress((void**)&wdec,  d_wdec);
    cudaGetSymbolAddress((void**)&preds, d_preds);

    const int RSMEM = (8192 + 16512 + 4608) * 4;  // 117248 B
    cudaFuncSetAttribute(recurrence, cudaFuncAttributeMaxDynamicSharedMemorySize, RSMEM);

    // 1) xr = reshape(x) @ conv_w + conv_b     [5376,4096]x[4096,512]
    {
        dim3 grid(N_ / BN, MR_ / BM);            // (8, 84)
        gemm_tf32<<<grid, 256>>>(x, conv_w, conv_b, xr, MR_, N_, KIN_);
    }
    // 2) xk = xr @ lstm_k + lstm_b             [5376,512]x[512,2048]
    {
        dim3 grid(G4N_ / BN, MR_ / BM);          // (32, 84)
        gemm_tf32<<<grid, 256>>>(xr, lstm_k, lstm_b, xk, MR_, G4N_, N_);
    }
    // 3) Wdec = lstm_k + lstm_rk
    {
        int n4 = (N_ * G4N_) / 4;
        add_w<<<(n4 + 255) / 256, 256>>>(lstm_k, lstm_rk, wdec, n4);
    }
    // 4) encoder (168 steps) + decoder (24 steps), persistent
    recurrence<<<RGRID, 512, RSMEM>>>(lstm_rk, wdec, xk, lstm_b, preds);
    // 5) out = preds @ dense_w + dense_b       [768,512]x[512,512]
    {
        dim3 grid(N_ / BN, (B_ * P_) / BM);      // (8, 12)
        gemm_tf32<<<grid, 256>>>(preds, dense_w, dense_b, out, B_ * P_, N_, N_);
    }
}

// round 11
// speedup vs baseline: 1.0201x; 1.0201x over previous
#include <cuda_runtime.h>
#include <cstdint>

// ---------------- problem constants ----------------
#define B_   32
#define H_   168
#define N_   512
#define F_   8
#define P_   24
#define KIN_ (N_ * F_)   // 4096
#define G4N_ (4 * N_)    // 2048
#define MR_  (B_ * H_)   // 5376
#define RGRID 128        // recurrence grid (all co-resident; 128 <= 148 SMs)
#define HS_  516         // hsh row stride (conflict-free A-frag loads)
#define WS_  24          // W smem row stride (conflict-free B-frag loads)
#define PS_  36          // psum b-stride (conflict-free partial STS/LDS)

typedef unsigned long long ull;

// ---------------- device scratch (no runtime allocation allowed) ----------------
__device__ float d_xr[(size_t)MR_ * N_];        // 11 MB
__device__ float d_xk[(size_t)MR_ * G4N_];      // 44 MB (includes lstm_b)
__device__ float d_wdec[(size_t)N_ * G4N_];     // 4 MB  (lstm_k + lstm_rk)
__device__ float d_h[2][B_ * N_];               // h[b][n], double buffered
__device__ float d_preds[(size_t)B_ * P_ * N_]; // 1.5 MB
__device__ unsigned g_flags[RGRID * 32];        // per-block monotonic publish flags
                                                // (stride 32 u32 = own 128B sector)

// ---------------- tf32 helpers ----------------
__device__ __forceinline__ unsigned f2tf(float x) {
    unsigned r;
    asm("cvt.rna.tf32.f32 %0, %1;" : "=r"(r) : "f"(x));
    return r;
}

__device__ __forceinline__ void mma_tf32(float* c, const unsigned* a,
                                         unsigned b0, unsigned b1) {
    asm volatile(
        "mma.sync.aligned.m16n8k8.row.col.f32.tf32.tf32.f32 "
        "{%0,%1,%2,%3},{%4,%5,%6,%7},{%8,%9},{%0,%1,%2,%3};"
        : "+f"(c[0]), "+f"(c[1]), "+f"(c[2]), "+f"(c[3])
        : "r"(a[0]), "r"(a[1]), "r"(a[2]), "r"(a[3]), "r"(b0), "r"(b1));
}

// ======================================================================
// C[M,N] = A[M,K] @ B[K,N] + bias[N], tf32 mma (R9 config: best measured).
// Block tile 128x64, 8 warps (4x2), warp tile 32x32, reg double-buffer.
// ======================================================================
#define BM 128
#define BN 64
#define BKt 32

__global__ __launch_bounds__(256) void gemm_tf32(
    const float* __restrict__ A, const float* __restrict__ Bw,
    const float* __restrict__ bias, float* __restrict__ C,
    int M, int N, int K)
{
    __shared__ float As[2][BM][BKt + 4];
    __shared__ float Bs[2][BKt][BN + 4];

    const int tid  = threadIdx.x;
    const int lane = tid & 31;
    const int warp = tid >> 5;
    const int wm = warp & 3;
    const int wn = warp >> 2;
    const int bm = blockIdx.y, bn = blockIdx.x;
    const int g  = lane >> 2;
    const int tg = lane & 3;

    const float* Ag = A + (size_t)bm * BM * K;
    const float* Bg = Bw + (size_t)bn * BN;

    int arow[4], akc[4];
#pragma unroll
    for (int i = 0; i < 4; i++) {
        int f4 = tid + i * 256;
        arow[i] = f4 >> 3;
        akc[i]  = (f4 & 7) << 2;
    }
    int brow[2], bnc[2];
#pragma unroll
    for (int i = 0; i < 2; i++) {
        int f4 = tid + i * 256;
        brow[i] = f4 >> 4;
        bnc[i]  = (f4 & 15) << 2;
    }

    float acc[2][4][4];
#pragma unroll
    for (int i = 0; i < 2; i++)
#pragma unroll
        for (int j = 0; j < 4; j++)
#pragma unroll
            for (int r = 0; r < 4; r++) acc[i][j][r] = 0.f;

    float4 ra[4], rb[2];
#pragma unroll
    for (int i = 0; i < 4; i++)
        ra[i] = *(const float4*)(Ag + (size_t)arow[i] * K + akc[i]);
#pragma unroll
    for (int i = 0; i < 2; i++)
        rb[i] = *(const float4*)(Bg + (size_t)brow[i] * N + bnc[i]);

    const int T = K / BKt;
    int buf = 0;
#pragma unroll
    for (int i = 0; i < 4; i++) {
        As[0][arow[i]][akc[i] + 0] = __uint_as_float(f2tf(ra[i].x));
        As[0][arow[i]][akc[i] + 1] = __uint_as_float(f2tf(ra[i].y));
        As[0][arow[i]][akc[i] + 2] = __uint_as_float(f2tf(ra[i].z));
        As[0][arow[i]][akc[i] + 3] = __uint_as_float(f2tf(ra[i].w));
    }
#pragma unroll
    for (int i = 0; i < 2; i++) {
        Bs[0][brow[i]][bnc[i] + 0] = __uint_as_float(f2tf(rb[i].x));
        Bs[0][brow[i]][bnc[i] + 1] = __uint_as_float(f2tf(rb[i].y));
        Bs[0][brow[i]][bnc[i] + 2] = __uint_as_float(f2tf(rb[i].z));
        Bs[0][brow[i]][bnc[i] + 3] = __uint_as_float(f2tf(rb[i].w));
    }
    __syncthreads();

    for (int t = 0; t < T; t++) {
        if (t + 1 < T) {
            const int kt = (t + 1) * BKt;
#pragma unroll
            for (int i = 0; i < 4; i++)
                ra[i] = *(const float4*)(Ag + (size_t)arow[i] * K + kt + akc[i]);
#pragma unroll
            for (int i = 0; i < 2; i++)
                rb[i] = *(const float4*)(Bg + (size_t)(kt + brow[i]) * N + bnc[i]);
        }

#pragma unroll
        for (int ks = 0; ks < 4; ks++) {
            const int k0 = ks * 8;
            unsigned a[2][4], b[4][2];
#pragma unroll
            for (int mi = 0; mi < 2; mi++) {
                int m0 = wm * 32 + mi * 16;
                a[mi][0] = __float_as_uint(As[buf][m0 + g    ][k0 + tg    ]);
                a[mi][1] = __float_as_uint(As[buf][m0 + g + 8][k0 + tg    ]);
                a[mi][2] = __float_as_uint(As[buf][m0 + g    ][k0 + tg + 4]);
                a[mi][3] = __float_as_uint(As[buf][m0 + g + 8][k0 + tg + 4]);
            }
#pragma unroll
            for (int ni = 0; ni < 4; ni++) {
                int n0 = wn * 32 + ni * 8;
                b[ni][0] = __float_as_uint(Bs[buf][k0 + tg    ][n0 + g]);
                b[ni][1] = __float_as_uint(Bs[buf][k0 + tg + 4][n0 + g]);
            }
#pragma unroll
            for (int mi = 0; mi < 2; mi++)
#pragma unroll
                for (int ni = 0; ni < 4; ni++)
                    mma_tf32(acc[mi][ni], a[mi], b[ni][0], b[ni][1]);
        }

        if (t + 1 < T) {
            const int nb = buf ^ 1;
#pragma unroll
            for (int i = 0; i < 4; i++) {
                As[nb][arow[i]][akc[i] + 0] = __uint_as_float(f2tf(ra[i].x));
                As[nb][arow[i]][akc[i] + 1] = __uint_as_float(f2tf(ra[i].y));
                As[nb][arow[i]][akc[i] + 2] = __uint_as_float(f2tf(ra[i].z));
                As[nb][arow[i]][akc[i] + 3] = __uint_as_float(f2tf(ra[i].w));
            }
#pragma unroll
            for (int i = 0; i < 2; i++) {
                Bs[nb][brow[i]][bnc[i] + 0] = __uint_as_float(f2tf(rb[i].x));
                Bs[nb][brow[i]][bnc[i] + 1] = __uint_as_float(f2tf(rb[i].y));
                Bs[nb][brow[i]][bnc[i] + 2] = __uint_as_float(f2tf(rb[i].z));
                Bs[nb][brow[i]][bnc[i] + 3] = __uint_as_float(f2tf(rb[i].w));
            }
            __syncthreads();
            buf = nb;
        }
    }

#pragma unroll
    for (int mi = 0; mi < 2; mi++) {
        int r0 = bm * BM + wm * 32 + mi * 16 + g;
#pragma unroll
        for (int ni = 0; ni < 4; ni++) {
            int c0 = bn * BN + wn * 32 + ni * 8 + tg * 2;
            float b0 = bias[c0], b1 = bias[c0 + 1];
            *(float2*)(C + (size_t)r0 * N + c0) =
                make_float2(acc[mi][ni][0] + b0, acc[mi][ni][1] + b1);
            *(float2*)(C + (size_t)(r0 + 8) * N + c0) =
                make_float2(acc[mi][ni][2] + b0, acc[mi][ni][3] + b1);
        }
    }
}

// ======================================================================
// Wdec = lstm_k + lstm_rk (elementwise, float4)
// ======================================================================
__global__ void add_w(const float* __restrict__ a, const float* __restrict__ b,
                      float* __restrict__ o, int n4)
{
    int i = blockIdx.x * blockDim.x + threadIdx.x;
    if (i < n4) {
        float4 x = ((const float4*)a)[i];
        float4 y = ((const float4*)b)[i];
        ((float4*)o)[i] = make_float4(x.x + y.x, x.y + y.y, x.z + y.z, x.w + y.w);
    }
}

// ======================================================================
// Persistent recurrence kernel (R11): DATAFLOW flags, no global barrier.
//  - per-block monotonic publish flag (release-store after h write)
//  - each lane acquire-polls exactly the producer block whose h it reads
//  - warp-private staging: warp (kg,mi) loads h rows [mi*16,+16) x
//    cols [kg*64,+64) straight from L2 into its own hsh slice
//  - skew pipelines across steps instead of summing at a barrier
// ======================================================================
__device__ __forceinline__ float sigf(float x) { return 1.f / (1.f + expf(-x)); }

// stage one W slice (16 cols starting nc0) as hi/lo tf32 into smem
__device__ __forceinline__ void stage_w(const float* __restrict__ W, int nc0,
                                        unsigned* wHi, unsigned* wLo, int tid)
{
    for (int i = tid; i < 2048; i += 512) {
        int k = i >> 2, gate = i & 3;
        float4 w = *(const float4*)(W + (size_t)k * G4N_ + gate * 512 + nc0);
        unsigned h0 = f2tf(w.x), h1 = f2tf(w.y), h2 = f2tf(w.z), h3 = f2tf(w.w);
        unsigned l0 = __float_as_uint(w.x - __uint_as_float(h0));
        unsigned l1 = __float_as_uint(w.y - __uint_as_float(h1));
        unsigned l2 = __float_as_uint(w.z - __uint_as_float(h2));
        unsigned l3 = __float_as_uint(w.w - __uint_as_float(h3));
        *(uint4*)&wHi[k * WS_ + gate * 4] = make_uint4(h0, h1, h2, h3);
        *(uint4*)&wLo[k * WS_ + gate * 4] = make_uint4(l0, l1, l2, l3);
    }
}

__global__ __launch_bounds__(512, 1) void recurrence(
    const float* __restrict__ Wenc,   // lstm_rk [512][2048]
    const float* __restrict__ Wdec,   // [512][2048]
    const float* __restrict__ xk,     // [B*H][2048] (bias folded in)
    const float* __restrict__ lb,     // lstm_b [2048]
    float* __restrict__ preds)        // [B][P][N]
{
    extern __shared__ float sm[];
    unsigned* wHi = (unsigned*)sm;            // 12288 u32
    unsigned* wLo = (unsigned*)(sm + 12288);  // 12288 u32
    float* hsh    = sm + 24576;               // 32 x 516 = 16512 floats
    float* psum   = sm + 41088;               // 8 x 16 x 36 = 4608 floats

    const int tid  = threadIdx.x;
    const int lane = tid & 31;
    const int warp = tid >> 5;
    const int g    = lane >> 2;
    const int tg   = lane & 3;
    const int kg   = warp & 7;     // k-split group
    const int mi   = warp >> 3;    // row half
    const int m0   = mi * 16;
    const int nc0  = blockIdx.x * 4;

    // ---- replay-safe flag base (all flags equal at launch) ----
    const unsigned base = g_flags[blockIdx.x * 32];

    // ---- stage encoder W hi/lo once ----
    stage_w(Wenc, nc0, wHi, wLo, tid);

    // ---- init: publish h_0 = 0 ----
    const int b  = tid & 31;
    const int cu = tid >> 5;
    float lbr[4], cst = 0.f, pf[4];
    if (tid < 128) {
        d_h[0][(size_t)b * N_ + nc0 + cu] = 0.f;
#pragma unroll
        for (int q = 0; q < 4; q++) lbr[q] = lb[q * 512 + nc0 + cu];
        const float* xp = xk + ((size_t)b * H_) * G4N_ + nc0 + cu;
        pf[0] = __ldg(xp);
        pf[1] = __ldg(xp + 512);
        pf[2] = __ldg(xp + 1024);
        pf[3] = __ldg(xp + 1536);
    }
    __syncthreads();
    if (tid == 0)
        asm volatile("st.release.gpu.global.u32 [%0], %1;"
                     :: "l"(&g_flags[blockIdx.x * 32]), "r"(base + 1u) : "memory");

    // ---- per-lane producer assignment ----
    const int jj = kg * 16 + (lane & 15);              // producer block index
    const unsigned* flagp = &g_flags[jj * 32];
    const int half = lane >> 4;                         // 0/1
    const int r0s  = m0 + half * 8;                     // 8 staging rows
    const int scol = kg * 64 + (lane & 15) * 4;         // hsh col for block jj

    for (int s = 0; s < H_ + P_; s++) {
        // enc -> dec transition (one time; all warps aligned at loop top)
        if (s == H_) {
            stage_w(Wdec, nc0, wHi, wLo, tid);
            __syncthreads();
        }

        // ---- wait for producer jj to publish h_s, then stage its slice ----
        {
            const unsigned tgt = base + 1u + (unsigned)s;
            unsigned v;
            do {
                asm volatile("ld.acquire.gpu.global.u32 %0, [%1];"
                             : "=r"(v) : "l"(flagp) : "memory");
            } while ((int)(v - tgt) < 0);
        }
        {
            const float4* hb = (const float4*)d_h[s & 1];  // [b*128 + n4]
            float4 hv[8];
#pragma unroll
            for (int r = 0; r < 8; r++)
                hv[r] = __ldcg(hb + (size_t)(r0s + r) * 128 + jj);
#pragma unroll
            for (int r = 0; r < 8; r++)
                *(float4*)&hsh[(r0s + r) * HS_ + scol] = hv[r];
        }
        __syncwarp();

        // ---- tensor-core partial GEMM: rows [m0,m0+16), k-slice [kg*64,+64) ----
        float acc0[4] = {0.f, 0.f, 0.f, 0.f};
        float acc1[4] = {0.f, 0.f, 0.f, 0.f};
#pragma unroll
        for (int f = 0; f < 8; f++) {
            const int k0 = kg * 64 + f * 8;
            float a0 = hsh[(m0 + g    ) * HS_ + k0 + tg    ];
            float a1 = hsh[(m0 + g + 8) * HS_ + k0 + tg    ];
            float a2 = hsh[(m0 + g    ) * HS_ + k0 + tg + 4];
            float a3 = hsh[(m0 + g + 8) * HS_ + k0 + tg + 4];
            unsigned ahi[4], alo[4];
            ahi[0] = f2tf(a0); alo[0] = __float_as_uint(a0 - __uint_as_float(ahi[0]));
            ahi[1] = f2tf(a1); alo[1] = __float_as_uint(a1 - __uint_as_float(ahi[1]));
            ahi[2] = f2tf(a2); alo[2] = __float_as_uint(a2 - __uint_as_float(ahi[2]));
            ahi[3] = f2tf(a3); alo[3] = __float_as_uint(a3 - __uint_as_float(ahi[3]));
            unsigned bh0 = wHi[(k0 + tg    ) * WS_ + g];
            unsigned bh1 = wHi[(k0 + tg + 4) * WS_ + g];
            unsigned bh2 = wHi[(k0 + tg    ) * WS_ + 8 + g];
            unsigned bh3 = wHi[(k0 + tg + 4) * WS_ + 8 + g];
            unsigned bl0 = wLo[(k0 + tg    ) * WS_ + g];
            unsigned bl1 = wLo[(k0 + tg + 4) * WS_ + g];
            unsigned bl2 = wLo[(k0 + tg    ) * WS_ + 8 + g];
            unsigned bl3 = wLo[(k0 + tg + 4) * WS_ + 8 + g];
            mma_tf32(acc0, ahi, bh0, bh1);
            mma_tf32(acc0, alo, bh0, bh1);
            mma_tf32(acc0, ahi, bl0, bl1);
            mma_tf32(acc1, ahi, bh2, bh3);
            mma_tf32(acc1, alo, bh2, bh3);
            mma_tf32(acc1, ahi, bl2, bl3);
        }
        // ---- stash partials ----
        {
            const int c0 = tg * 2, r0 = m0 + g;
            psum[(kg * 16 + c0        ) * PS_ + r0    ] = acc0[0];
            psum[(kg * 16 + c0 + 1    ) * PS_ + r0    ] = acc0[1];
            psum[(kg * 16 + c0        ) * PS_ + r0 + 8] = acc0[2];
            psum[(kg * 16 + c0 + 1    ) * PS_ + r0 + 8] = acc0[3];
            psum[(kg * 16 + 8 + c0    ) * PS_ + r0    ] = acc1[0];
            psum[(kg * 16 + 8 + c0 + 1) * PS_ + r0    ] = acc1[1];
            psum[(kg * 16 + 8 + c0    ) * PS_ + r0 + 8] = acc1[2];
            psum[(kg * 16 + 8 + c0 + 1) * PS_ + r0 + 8] = acc1[3];
        }
        __syncthreads();   // psum ready (also protects psum reuse next step)

        // ---- cell update: thread (b, cu) handles hidden col nc0+cu ----
        if (tid < 128) {
            float pfn[4];
            if (s + 1 < H_) {
                const float* xp = xk + ((size_t)b * H_ + (s + 1)) * G4N_ + nc0 + cu;
                pfn[0] = __ldg(xp);
                pfn[1] = __ldg(xp + 512);
                pfn[2] = __ldg(xp + 1024);
                pfn[3] = __ldg(xp + 1536);
            } else {
                pfn[0] = lbr[0]; pfn[1] = lbr[1]; pfn[2] = lbr[2]; pfn[3] = lbr[3];
            }

            float z[4];
#pragma unroll
            for (int q = 0; q < 4; q++) {
                const int n = q * 4 + cu;
                float accv = pf[q];
#pragma unroll
                for (int kk = 0; kk < 8; kk++)
                    accv += psum[(kk * 16 + n) * PS_ + b];
                z[q] = accv;
            }
            float ii = sigf(z[0]), ff = sigf(z[1]);
            float gg = tanhf(z[2]), oo = sigf(z[3]);
            cst = ff * cst + ii * gg;
            float hn = oo * tanhf(cst);
            d_h[(s + 1) & 1][(size_t)b * N_ + nc0 + cu] = hn;
            if (s >= H_)
                preds[((size_t)b * P_ + (s - H_)) * N_ + nc0 + cu] = hn;

            pf[0] = pfn[0]; pf[1] = pfn[1]; pf[2] = pfn[2]; pf[3] = pfn[3];
        }
        __syncthreads();   // h stores complete before flag release

        if (tid == 0)
            asm volatile("st.release.gpu.global.u32 [%0], %1;"
                         :: "l"(&g_flags[blockIdx.x * 32]), "r"(base + 2u + (unsigned)s)
                         : "memory");
    }
}

// ======================================================================
// launch
// ======================================================================
extern "C" void kernel_launch(void* const* d_in, const int* in_sizes, int n_in,
                              void* d_out, int out_size)
{
    const float* x       = (const float*)d_in[0];
    const float* conv_w  = (const float*)d_in[1];
    const float* conv_b  = (const float*)d_in[2];
    const float* lstm_k  = (const float*)d_in[3];
    const float* lstm_rk = (const float*)d_in[4];
    const float* lstm_b  = (const float*)d_in[5];
    const float* dense_w = (const float*)d_in[6];
    const float* dense_b = (const float*)d_in[7];
    float* out = (float*)d_out;

    float *xr, *xk, *wdec, *preds;
    cudaGetSymbolAddress((void**)&xr,    d_xr);
    cudaGetSymbolAddress((void**)&xk,    d_xk);
    cudaGetSymbolAddress((void**)&wdec,  d_wdec);
    cudaGetSymbolAddress((void**)&preds, d_preds);

    const int RSMEM = (12288 + 12288 + 16512 + 4608) * 4;  // 182784 B
    cudaFuncSetAttribute(recurrence, cudaFuncAttributeMaxDynamicSharedMemorySize, RSMEM);

    // 1) xr = reshape(x) @ conv_w + conv_b     [5376,4096]x[4096,512]
    {
        dim3 grid(N_ / BN, MR_ / BM);
        gemm_tf32<<<grid, 256>>>(x, conv_w, conv_b, xr, MR_, N_, KIN_);
    }
    // 2) xk = xr @ lstm_k + lstm_b             [5376,512]x[512,2048]
    {
        dim3 grid(G4N_ / BN, MR_ / BM);
        gemm_tf32<<<grid, 256>>>(xr, lstm_k, lstm_b, xk, MR_, G4N_, N_);
    }
    // 3) Wdec = lstm_k + lstm_rk
    {
        int n4 = (N_ * G4N_) / 4;
        add_w<<<(n4 + 255) / 256, 256>>>(lstm_k, lstm_rk, wdec, n4);
    }
    // 4) encoder (168 steps) + decoder (24 steps), persistent dataflow
    recurrence<<<RGRID, 512, RSMEM>>>(lstm_rk, wdec, xk, lstm_b, preds);
    // 5) out = preds @ dense_w + dense_b       [768,512]x[512,512]
    {
        dim3 grid(N_ / BN, (B_ * P_) / BM);
        gemm_tf32<<<grid, 256>>>(preds, dense_w, dense_b, out, B_ * P_, N_, N_);
    }
}

// round 13
// speedup vs baseline: 1.0348x; 1.0144x over previous
#include <cuda_runtime.h>
#include <cstdint>

// ---------------- problem constants ----------------
#define B_   32
#define H_   168
#define N_   512
#define F_   8
#define P_   24
#define KIN_ (N_ * F_)   // 4096
#define G4N_ (4 * N_)    // 2048
#define MR_  (B_ * H_)   // 5376
#define RGRID 128        // recurrence grid (all co-resident; 128 <= 148 SMs)
#define HS_  516         // hsh row stride (conflict-free A-frag loads)
#define WS_  24          // W smem row stride (conflict-free B-frag loads)
#define PS_  36          // psum b-stride (conflict-free partial STS/LDS)

typedef unsigned long long ull;

// ---------------- device scratch (no runtime allocation allowed) ----------------
__device__ float d_xr[(size_t)MR_ * N_];        // 11 MB
__device__ float d_xk[(size_t)MR_ * G4N_];      // 44 MB (includes lstm_b)
__device__ float d_wdec[(size_t)N_ * G4N_];     // 4 MB  (lstm_k + lstm_rk)
__device__ float d_h[2][B_ * N_];               // h[b][n], double buffered
__device__ float d_preds[(size_t)B_ * P_ * N_]; // 1.5 MB
__device__ unsigned g_flags[RGRID * 32];        // per-block monotonic publish flags

// ---------------- tf32 helpers ----------------
__device__ __forceinline__ unsigned f2tf(float x) {
    unsigned r;
    asm("cvt.rna.tf32.f32 %0, %1;" : "=r"(r) : "f"(x));
    return r;
}

__device__ __forceinline__ void mma_tf32(float* c, const unsigned* a,
                                         unsigned b0, unsigned b1) {
    asm volatile(
        "mma.sync.aligned.m16n8k8.row.col.f32.tf32.tf32.f32 "
        "{%0,%1,%2,%3},{%4,%5,%6,%7},{%8,%9},{%0,%1,%2,%3};"
        : "+f"(c[0]), "+f"(c[1]), "+f"(c[2]), "+f"(c[3])
        : "r"(a[0]), "r"(a[1]), "r"(a[2]), "r"(a[3]), "r"(b0), "r"(b1));
}

// ======================================================================
// C[M,N] = A[M,K] @ B[K,N] + bias[N], tf32 mma (R9 config, best measured).
// ======================================================================
#define BM 128
#define BN 64
#define BKt 32

__global__ __launch_bounds__(256) void gemm_tf32(
    const float* __restrict__ A, const float* __restrict__ Bw,
    const float* __restrict__ bias, float* __restrict__ C,
    int M, int N, int K)
{
    __shared__ float As[2][BM][BKt + 4];
    __shared__ float Bs[2][BKt][BN + 4];

    const int tid  = threadIdx.x;
    const int lane = tid & 31;
    const int warp = tid >> 5;
    const int wm = warp & 3;
    const int wn = warp >> 2;
    const int bm = blockIdx.y, bn = blockIdx.x;
    const int g  = lane >> 2;
    const int tg = lane & 3;

    const float* Ag = A + (size_t)bm * BM * K;
    const float* Bg = Bw + (size_t)bn * BN;

    int arow[4], akc[4];
#pragma unroll
    for (int i = 0; i < 4; i++) {
        int f4 = tid + i * 256;
        arow[i] = f4 >> 3;
        akc[i]  = (f4 & 7) << 2;
    }
    int brow[2], bnc[2];
#pragma unroll
    for (int i = 0; i < 2; i++) {
        int f4 = tid + i * 256;
        brow[i] = f4 >> 4;
        bnc[i]  = (f4 & 15) << 2;
    }

    float acc[2][4][4];
#pragma unroll
    for (int i = 0; i < 2; i++)
#pragma unroll
        for (int j = 0; j < 4; j++)
#pragma unroll
            for (int r = 0; r < 4; r++) acc[i][j][r] = 0.f;

    float4 ra[4], rb[2];
#pragma unroll
    for (int i = 0; i < 4; i++)
        ra[i] = *(const float4*)(Ag + (size_t)arow[i] * K + akc[i]);
#pragma unroll
    for (int i = 0; i < 2; i++)
        rb[i] = *(const float4*)(Bg + (size_t)brow[i] * N + bnc[i]);

    const int T = K / BKt;
    int buf = 0;
#pragma unroll
    for (int i = 0; i < 4; i++) {
        As[0][arow[i]][akc[i] + 0] = __uint_as_float(f2tf(ra[i].x));
        As[0][arow[i]][akc[i] + 1] = __uint_as_float(f2tf(ra[i].y));
        As[0][arow[i]][akc[i] + 2] = __uint_as_float(f2tf(ra[i].z));
        As[0][arow[i]][akc[i] + 3] = __uint_as_float(f2tf(ra[i].w));
    }
#pragma unroll
    for (int i = 0; i < 2; i++) {
        Bs[0][brow[i]][bnc[i] + 0] = __uint_as_float(f2tf(rb[i].x));
        Bs[0][brow[i]][bnc[i] + 1] = __uint_as_float(f2tf(rb[i].y));
        Bs[0][brow[i]][bnc[i] + 2] = __uint_as_float(f2tf(rb[i].z));
        Bs[0][brow[i]][bnc[i] + 3] = __uint_as_float(f2tf(rb[i].w));
    }
    __syncthreads();

    for (int t = 0; t < T; t++) {
        if (t + 1 < T) {
            const int kt = (t + 1) * BKt;
#pragma unroll
            for (int i = 0; i < 4; i++)
                ra[i] = *(const float4*)(Ag + (size_t)arow[i] * K + kt + akc[i]);
#pragma unroll
            for (int i = 0; i < 2; i++)
                rb[i] = *(const float4*)(Bg + (size_t)(kt + brow[i]) * N + bnc[i]);
        }

#pragma unroll
        for (int ks = 0; ks < 4; ks++) {
            const int k0 = ks * 8;
            unsigned a[2][4], b[4][2];
#pragma unroll
            for (int mi = 0; mi < 2; mi++) {
                int m0 = wm * 32 + mi * 16;
                a[mi][0] = __float_as_uint(As[buf][m0 + g    ][k0 + tg    ]);
                a[mi][1] = __float_as_uint(As[buf][m0 + g + 8][k0 + tg    ]);
                a[mi][2] = __float_as_uint(As[buf][m0 + g    ][k0 + tg + 4]);
                a[mi][3] = __float_as_uint(As[buf][m0 + g + 8][k0 + tg + 4]);
            }
#pragma unroll
            for (int ni = 0; ni < 4; ni++) {
                int n0 = wn * 32 + ni * 8;
                b[ni][0] = __float_as_uint(Bs[buf][k0 + tg    ][n0 + g]);
                b[ni][1] = __float_as_uint(Bs[buf][k0 + tg + 4][n0 + g]);
            }
#pragma unroll
            for (int mi = 0; mi < 2; mi++)
#pragma unroll
                for (int ni = 0; ni < 4; ni++)
                    mma_tf32(acc[mi][ni], a[mi], b[ni][0], b[ni][1]);
        }

        if (t + 1 < T) {
            const int nb = buf ^ 1;
#pragma unroll
            for (int i = 0; i < 4; i++) {
                As[nb][arow[i]][akc[i] + 0] = __uint_as_float(f2tf(ra[i].x));
                As[nb][arow[i]][akc[i] + 1] = __uint_as_float(f2tf(ra[i].y));
                As[nb][arow[i]][akc[i] + 2] = __uint_as_float(f2tf(ra[i].z));
                As[nb][arow[i]][akc[i] + 3] = __uint_as_float(f2tf(ra[i].w));
            }
#pragma unroll
            for (int i = 0; i < 2; i++) {
                Bs[nb][brow[i]][bnc[i] + 0] = __uint_as_float(f2tf(rb[i].x));
                Bs[nb][brow[i]][bnc[i] + 1] = __uint_as_float(f2tf(rb[i].y));
                Bs[nb][brow[i]][bnc[i] + 2] = __uint_as_float(f2tf(rb[i].z));
                Bs[nb][brow[i]][bnc[i] + 3] = __uint_as_float(f2tf(rb[i].w));
            }
            __syncthreads();
            buf = nb;
        }
    }

#pragma unroll
    for (int mi = 0; mi < 2; mi++) {
        int r0 = bm * BM + wm * 32 + mi * 16 + g;
#pragma unroll
        for (int ni = 0; ni < 4; ni++) {
            int c0 = bn * BN + wn * 32 + ni * 8 + tg * 2;
            float b0 = bias[c0], b1 = bias[c0 + 1];
            *(float2*)(C + (size_t)r0 * N + c0) =
                make_float2(acc[mi][ni][0] + b0, acc[mi][ni][1] + b1);
            *(float2*)(C + (size_t)(r0 + 8) * N + c0) =
                make_float2(acc[mi][ni][2] + b0, acc[mi][ni][3] + b1);
        }
    }
}

// ======================================================================
// Wdec = lstm_k + lstm_rk (elementwise, float4)
// ======================================================================
__global__ void add_w(const float* __restrict__ a, const float* __restrict__ b,
                      float* __restrict__ o, int n4)
{
    int i = blockIdx.x * blockDim.x + threadIdx.x;
    if (i < n4) {
        float4 x = ((const float4*)a)[i];
        float4 y = ((const float4*)b)[i];
        ((float4*)o)[i] = make_float4(x.x + y.x, x.y + y.y, x.z + y.z, x.w + y.w);
    }
}

// ======================================================================
// Persistent recurrence kernel (R13): R12 chain surgery + ACQUIRE poll.
//  - ONE __syncthreads per step (psum double-buffered by step parity)
//  - update warps: named barrier (128) + release; mma warps flow to next poll
//  - xk prefetch issued at step top (fully hidden)
//  - poll with ld.acquire.gpu (formally synchronizes-with producer release;
//    the R12 weak-poll+fence was a data race and corrupted h)
//  - 4 independent mma accumulator chains
// ======================================================================
__device__ __forceinline__ float sigf(float x) { return 1.f / (1.f + expf(-x)); }

__device__ __forceinline__ void stage_w(const float* __restrict__ W, int nc0,
                                        unsigned* wHi, unsigned* wLo, int tid)
{
    for (int i = tid; i < 2048; i += 512) {
        int k = i >> 2, gate = i & 3;
        float4 w = *(const float4*)(W + (size_t)k * G4N_ + gate * 512 + nc0);
        unsigned h0 = f2tf(w.x), h1 = f2tf(w.y), h2 = f2tf(w.z), h3 = f2tf(w.w);
        unsigned l0 = __float_as_uint(w.x - __uint_as_float(h0));
        unsigned l1 = __float_as_uint(w.y - __uint_as_float(h1));
        unsigned l2 = __float_as_uint(w.z - __uint_as_float(h2));
        unsigned l3 = __float_as_uint(w.w - __uint_as_float(h3));
        *(uint4*)&wHi[k * WS_ + gate * 4] = make_uint4(h0, h1, h2, h3);
        *(uint4*)&wLo[k * WS_ + gate * 4] = make_uint4(l0, l1, l2, l3);
    }
}

__global__ __launch_bounds__(512, 1) void recurrence(
    const float* __restrict__ Wenc,   // lstm_rk [512][2048]
    const float* __restrict__ Wdec,   // [512][2048]
    const float* __restrict__ xk,     // [B*H][2048] (bias folded in)
    const float* __restrict__ lb,     // lstm_b [2048]
    float* __restrict__ preds)        // [B][P][N]
{
    extern __shared__ float sm[];
    unsigned* wHi = (unsigned*)sm;            // 12288 u32
    unsigned* wLo = (unsigned*)(sm + 12288);  // 12288 u32
    float* hsh    = sm + 24576;               // 32 x 516 = 16512 floats
    float* psumB  = sm + 41088;               // 2 x 4608 floats (step parity)

    const int tid  = threadIdx.x;
    const int lane = tid & 31;
    const int warp = tid >> 5;
    const int g    = lane >> 2;
    const int tg   = lane & 3;
    const int kg   = warp & 7;     // k-split group
    const int mi   = warp >> 3;    // row half
    const int m0   = mi * 16;
    const int nc0  = blockIdx.x * 4;

    // replay-safe flag base (all flags equal at launch)
    const unsigned base = g_flags[blockIdx.x * 32];

    stage_w(Wenc, nc0, wHi, wLo, tid);

    // ---- init: publish h_0 = 0 ----
    const int b  = tid & 31;
    const int cu = tid >> 5;
    float lbr[4], cst = 0.f, pf[4];
    if (tid < 128) {
        d_h[0][(size_t)b * N_ + nc0 + cu] = 0.f;
#pragma unroll
        for (int q = 0; q < 4; q++) lbr[q] = lb[q * 512 + nc0 + cu];
        const float* xp = xk + ((size_t)b * H_) * G4N_ + nc0 + cu;
        pf[0] = __ldg(xp);
        pf[1] = __ldg(xp + 512);
        pf[2] = __ldg(xp + 1024);
        pf[3] = __ldg(xp + 1536);
    }
    __syncthreads();
    if (tid == 0)
        asm volatile("st.release.gpu.global.u32 [%0], %1;"
                     :: "l"(&g_flags[blockIdx.x * 32]), "r"(base + 1u) : "memory");

    // per-lane producer assignment
    const int jj = kg * 16 + (lane & 15);              // producer block index
    const unsigned* flagp = &g_flags[jj * 32];
    const int half = lane >> 4;
    const int r0s  = m0 + half * 8;
    const int scol = kg * 64 + (lane & 15) * 4;

    for (int s = 0; s < H_ + P_; s++) {
        if (s == H_) {                 // enc -> dec transition (one time)
            stage_w(Wdec, nc0, wHi, wLo, tid);
            __syncthreads();
        }

        // ---- issue next-step xk prefetch NOW (fully hidden) ----
        float pfn[4];
        if (tid < 128) {
            if (s + 1 < H_) {
                const float* xp = xk + ((size_t)b * H_ + (s + 1)) * G4N_ + nc0 + cu;
                pfn[0] = __ldg(xp);
                pfn[1] = __ldg(xp + 512);
                pfn[2] = __ldg(xp + 1024);
                pfn[3] = __ldg(xp + 1536);
            } else {
                pfn[0] = lbr[0]; pfn[1] = lbr[1]; pfn[2] = lbr[2]; pfn[3] = lbr[3];
            }
        }

        // ---- wait for producer jj (ACQUIRE poll: synchronizes-with release) ----
        {
            const unsigned tgt = base + 1u + (unsigned)s;
            unsigned v;
            do {
                asm volatile("ld.acquire.gpu.global.u32 %0, [%1];"
                             : "=r"(v) : "l"(flagp) : "memory");
            } while ((int)(v - tgt) < 0);
        }
        // ---- stage producer jj's h slice ----
        {
            const float4* hb = (const float4*)d_h[s & 1];
            float4 hv[8];
#pragma unroll
            for (int r = 0; r < 8; r++)
                hv[r] = __ldcg(hb + (size_t)(r0s + r) * 128 + jj);
#pragma unroll
            for (int r = 0; r < 8; r++)
                *(float4*)&hsh[(r0s + r) * HS_ + scol] = hv[r];
        }
        __syncwarp();

        // ---- mma: rows [m0,m0+16), k-slice [kg*64,+64), 4 acc chains ----
        float ac0[2][4] = {{0.f,0.f,0.f,0.f},{0.f,0.f,0.f,0.f}};
        float ac1[2][4] = {{0.f,0.f,0.f,0.f},{0.f,0.f,0.f,0.f}};
#pragma unroll
        for (int f = 0; f < 8; f++) {
            const int k0 = kg * 64 + f * 8;
            const int c = f & 1;
            float a0 = hsh[(m0 + g    ) * HS_ + k0 + tg    ];
            float a1 = hsh[(m0 + g + 8) * HS_ + k0 + tg    ];
            float a2 = hsh[(m0 + g    ) * HS_ + k0 + tg + 4];
            float a3 = hsh[(m0 + g + 8) * HS_ + k0 + tg + 4];
            unsigned ahi[4], alo[4];
            ahi[0] = f2tf(a0); alo[0] = __float_as_uint(a0 - __uint_as_float(ahi[0]));
            ahi[1] = f2tf(a1); alo[1] = __float_as_uint(a1 - __uint_as_float(ahi[1]));
            ahi[2] = f2tf(a2); alo[2] = __float_as_uint(a2 - __uint_as_float(ahi[2]));
            ahi[3] = f2tf(a3); alo[3] = __float_as_uint(a3 - __uint_as_float(ahi[3]));
            unsigned bh0 = wHi[(k0 + tg    ) * WS_ + g];
            unsigned bh1 = wHi[(k0 + tg + 4) * WS_ + g];
            unsigned bh2 = wHi[(k0 + tg    ) * WS_ + 8 + g];
            unsigned bh3 = wHi[(k0 + tg + 4) * WS_ + 8 + g];
            unsigned bl0 = wLo[(k0 + tg    ) * WS_ + g];
            unsigned bl1 = wLo[(k0 + tg + 4) * WS_ + g];
            unsigned bl2 = wLo[(k0 + tg    ) * WS_ + 8 + g];
            unsigned bl3 = wLo[(k0 + tg + 4) * WS_ + 8 + g];
            mma_tf32(ac0[c], ahi, bh0, bh1);
            mma_tf32(ac0[c], alo, bh0, bh1);
            mma_tf32(ac0[c], ahi, bl0, bl1);
            mma_tf32(ac1[c], ahi, bh2, bh3);
            mma_tf32(ac1[c], alo, bh2, bh3);
            mma_tf32(ac1[c], ahi, bl2, bl3);
        }
        // ---- stash partials into parity psum ----
        {
            float* psum = psumB + (s & 1) * 4608;
            const int c0 = tg * 2, r0 = m0 + g;
            psum[(kg * 16 + c0        ) * PS_ + r0    ] = ac0[0][0] + ac0[1][0];
            psum[(kg * 16 + c0 + 1    ) * PS_ + r0    ] = ac0[0][1] + ac0[1][1];
            psum[(kg * 16 + c0        ) * PS_ + r0 + 8] = ac0[0][2] + ac0[1][2];
            psum[(kg * 16 + c0 + 1    ) * PS_ + r0 + 8] = ac0[0][3] + ac0[1][3];
            psum[(kg * 16 + 8 + c0    ) * PS_ + r0    ] = ac1[0][0] + ac1[1][0];
            psum[(kg * 16 + 8 + c0 + 1) * PS_ + r0    ] = ac1[0][1] + ac1[1][1];
            psum[(kg * 16 + 8 + c0    ) * PS_ + r0 + 8] = ac1[0][2] + ac1[1][2];
            psum[(kg * 16 + 8 + c0 + 1) * PS_ + r0 + 8] = ac1[0][3] + ac1[1][3];
        }
        __syncthreads();   // the ONLY block-wide barrier per step

        // ---- update (warps 0-3); mma-only warps flow to next poll ----
        if (tid < 128) {
            const float* psum = psumB + (s & 1) * 4608;
            float z[4];
#pragma unroll
            for (int q = 0; q < 4; q++) {
                const int n = q * 4 + cu;
                float accv = pf[q];
#pragma unroll
                for (int kk = 0; kk < 8; kk++)
                    accv += psum[(kk * 16 + n) * PS_ + b];
                z[q] = accv;
            }
            float ii = sigf(z[0]), ff = sigf(z[1]);
            float gg = tanhf(z[2]), oo = sigf(z[3]);
            cst = ff * cst + ii * gg;
            float hn = oo * tanhf(cst);
            d_h[(s + 1) & 1][(size_t)b * N_ + nc0 + cu] = hn;

            asm volatile("bar.sync 1, 128;" ::: "memory");
            if (tid == 0)
                asm volatile("st.release.gpu.global.u32 [%0], %1;"
                             :: "l"(&g_flags[blockIdx.x * 32]),
                                "r"(base + 2u + (unsigned)s) : "memory");

            if (s >= H_)
                preds[((size_t)b * P_ + (s - H_)) * N_ + nc0 + cu] = hn;

            pf[0] = pfn[0]; pf[1] = pfn[1]; pf[2] = pfn[2]; pf[3] = pfn[3];
        }
    }
}

// ======================================================================
// launch
// ======================================================================
extern "C" void kernel_launch(void* const* d_in, const int* in_sizes, int n_in,
                              void* d_out, int out_size)
{
    const float* x       = (const float*)d_in[0];
    const float* conv_w  = (const float*)d_in[1];
    const float* conv_b  = (const float*)d_in[2];
    const float* lstm_k  = (const float*)d_in[3];
    const float* lstm_rk = (const float*)d_in[4];
    const float* lstm_b  = (const float*)d_in[5];
    const float* dense_w = (const float*)d_in[6];
    const float* dense_b = (const float*)d_in[7];
    float* out = (float*)d_out;

    float *xr, *xk, *wdec, *preds;
    cudaGetSymbolAddress((void**)&xr,    d_xr);
    cudaGetSymbolAddress((void**)&xk,    d_xk);
    cudaGetSymbolAddress((void**)&wdec,  d_wdec);
    cudaGetSymbolAddress((void**)&preds, d_preds);

    const int RSMEM = (12288 + 12288 + 16512 + 2 * 4608) * 4;  // 201216 B
    cudaFuncSetAttribute(recurrence, cudaFuncAttributeMaxDynamicSharedMemorySize, RSMEM);

    // 1) xr = reshape(x) @ conv_w + conv_b     [5376,4096]x[4096,512]
    {
        dim3 grid(N_ / BN, MR_ / BM);
        gemm_tf32<<<grid, 256>>>(x, conv_w, conv_b, xr, MR_, N_, KIN_);
    }
    // 2) xk = xr @ lstm_k + lstm_b             [5376,512]x[512,2048]
    {
        dim3 grid(G4N_ / BN, MR_ / BM);
        gemm_tf32<<<grid, 256>>>(xr, lstm_k, lstm_b, xk, MR_, G4N_, N_);
    }
    // 3) Wdec = lstm_k + lstm_rk
    {
        int n4 = (N_ * G4N_) / 4;
        add_w<<<(n4 + 255) / 256, 256>>>(lstm_k, lstm_rk, wdec, n4);
    }
    // 4) encoder (168 steps) + decoder (24 steps), persistent dataflow
    recurrence<<<RGRID, 512, RSMEM>>>(lstm_rk, wdec, xk, lstm_b, preds);
    // 5) out = preds @ dense_w + dense_b       [768,512]x[512,512]
    {
        dim3 grid(N_ / BN, (B_ * P_) / BM);
        gemm_tf32<<<grid, 256>>>(preds, dense_w, dense_b, out, B_ * P_, N_, N_);
    }
}

// round 14
// speedup vs baseline: 1.0721x; 1.0361x over previous
#include <cuda_runtime.h>
#include <cstdint>

// ---------------- problem constants ----------------
#define B_   32
#define H_   168
#define N_   512
#define F_   8
#define P_   24
#define KIN_ (N_ * F_)   // 4096
#define G4N_ (4 * N_)    // 2048
#define MR_  (B_ * H_)   // 5376
#define RGRID 128        // recurrence grid (all co-resident; 128 <= 148 SMs)
#define HS_  516         // hsh row stride (conflict-free A-frag loads)
#define WS_  24          // W smem row stride (conflict-free B-frag loads)
#define PS_  36          // psum b-stride (conflict-free partial STS/LDS)

typedef unsigned long long ull;

// ---------------- device scratch (no runtime allocation allowed) ----------------
__device__ float d_xr[(size_t)MR_ * N_];        // 11 MB
__device__ float d_xk[(size_t)MR_ * G4N_];      // 44 MB (includes lstm_b)
__device__ float d_wdec[(size_t)N_ * G4N_];     // 4 MB  (lstm_k + lstm_rk)
__device__ float d_cw[(size_t)KIN_ * N_];       // conv_w pre-tf32 (8 MB)
__device__ float d_lk[(size_t)N_ * G4N_];       // lstm_k pre-tf32 (4 MB)
__device__ float d_dw[(size_t)N_ * N_];         // dense_w pre-tf32 (1 MB)
__device__ float d_h[2][B_ * N_];               // h[b][n], double buffered
__device__ float d_preds[(size_t)B_ * P_ * N_]; // 1.5 MB
__device__ unsigned g_flags[RGRID * 32];        // per-block monotonic publish flags

// ---------------- tf32 helpers ----------------
__device__ __forceinline__ unsigned f2tf(float x) {
    unsigned r;
    asm("cvt.rna.tf32.f32 %0, %1;" : "=r"(r) : "f"(x));
    return r;
}

__device__ __forceinline__ void mma_tf32(float* c, const unsigned* a,
                                         unsigned b0, unsigned b1) {
    asm volatile(
        "mma.sync.aligned.m16n8k8.row.col.f32.tf32.tf32.f32 "
        "{%0,%1,%2,%3},{%4,%5,%6,%7},{%8,%9},{%0,%1,%2,%3};"
        : "+f"(c[0]), "+f"(c[1]), "+f"(c[2]), "+f"(c[3])
        : "r"(a[0]), "r"(a[1]), "r"(a[2]), "r"(a[3]), "r"(b0), "r"(b1));
}

__device__ __forceinline__ unsigned sm_u32(const void* p) {
    return (unsigned)__cvta_generic_to_shared(p);
}

// ======================================================================
// prep: convert weights to tf32 (bit patterns in float) + wdec = lk + rk
// ======================================================================
__global__ void prep(const float* __restrict__ cw, const float* __restrict__ lk,
                     const float* __restrict__ rk, const float* __restrict__ dw)
{
    int i = blockIdx.x * blockDim.x + threadIdx.x;
    if (i < KIN_ * N_) d_cw[i] = __uint_as_float(f2tf(cw[i]));
    if (i < N_ * G4N_) {
        d_lk[i]   = __uint_as_float(f2tf(lk[i]));
        d_wdec[i] = lk[i] + rk[i];
    }
    if (i < N_ * N_) d_dw[i] = __uint_as_float(f2tf(dw[i]));
}

// ======================================================================
// C[M,N] = A[M,K] @ B[K,N] + bias[N], tf32 mma, cp.async 3-stage pipeline.
// A raw fp32 (cvt.rna after frag LDS), B pre-converted tf32 bits.
// Block tile 128x64, 8 warps (4x2), warp tile 32x32, K-tile 32.
// ======================================================================
#define BM 128
#define BN 64
#define BKt 32
#define NSTG 3
#define ASZ (BM * (BKt + 4))   // 4608 floats / stage
#define BSZ (BKt * (BN + 4))   // 2176 floats / stage

__global__ __launch_bounds__(256) void gemm_pipe(
    const float* __restrict__ A, const float* __restrict__ Bt,
    const float* __restrict__ bias, float* __restrict__ C,
    int M, int N, int K)
{
    extern __shared__ float smg[];
    float* As = smg;                 // NSTG * ASZ
    float* Bs = smg + NSTG * ASZ;    // NSTG * BSZ

    const int tid  = threadIdx.x;
    const int lane = tid & 31;
    const int warp = tid >> 5;
    const int wm = warp & 3;
    const int wn = warp >> 2;
    const int bm = blockIdx.y, bn = blockIdx.x;
    const int g  = lane >> 2;
    const int tg = lane & 3;

    const float* Ag = A + (size_t)bm * BM * K;
    const float* Bg = Bt + (size_t)bn * BN;

    int arow[4], akc[4];
#pragma unroll
    for (int i = 0; i < 4; i++) {
        int f4 = tid + i * 256;
        arow[i] = f4 >> 3;
        akc[i]  = (f4 & 7) << 2;
    }
    int brow[2], bnc[2];
#pragma unroll
    for (int i = 0; i < 2; i++) {
        int f4 = tid + i * 256;
        brow[i] = f4 >> 4;
        bnc[i]  = (f4 & 15) << 2;
    }

    float acc[2][4][4];
#pragma unroll
    for (int i = 0; i < 2; i++)
#pragma unroll
        for (int j = 0; j < 4; j++)
#pragma unroll
            for (int r = 0; r < 4; r++) acc[i][j][r] = 0.f;

    const int T = K / BKt;

    // issue one K-tile t into stage buffer `buf` (6 x 16B cp.async per thread)
    auto issue = [&](int t, int buf) {
#pragma unroll
        for (int i = 0; i < 4; i++) {
            unsigned dst = sm_u32(&As[buf * ASZ + arow[i] * (BKt + 4) + akc[i]]);
            const float* src = Ag + (size_t)arow[i] * K + t * BKt + akc[i];
            asm volatile("cp.async.cg.shared.global [%0], [%1], 16;"
                         :: "r"(dst), "l"(src));
        }
#pragma unroll
        for (int i = 0; i < 2; i++) {
            unsigned dst = sm_u32(&Bs[buf * BSZ + brow[i] * (BN + 4) + bnc[i]]);
            const float* src = Bg + (size_t)(t * BKt + brow[i]) * N + bnc[i];
            asm volatile("cp.async.cg.shared.global [%0], [%1], 16;"
                         :: "r"(dst), "l"(src));
        }
        asm volatile("cp.async.commit_group;");
    };

    // prologue: stages 0, 1
    issue(0, 0);
    issue(1, 1);

    for (int t = 0; t < T; t++) {
        asm volatile("cp.async.wait_group 1;");
        __syncthreads();

        if (t + 2 < T) issue(t + 2, (t + 2) % NSTG);
        else asm volatile("cp.async.commit_group;");   // keep group count monotone

        const int buf = t % NSTG;
        const float* Ab = As + buf * ASZ;
        const float* Bb = Bs + buf * BSZ;

#pragma unroll
        for (int ks = 0; ks < 4; ks++) {
            const int k0 = ks * 8;
            unsigned a[2][4], b[4][2];
#pragma unroll
            for (int mi = 0; mi < 2; mi++) {
                int m0 = wm * 32 + mi * 16;
                a[mi][0] = f2tf(Ab[(m0 + g    ) * (BKt + 4) + k0 + tg    ]);
                a[mi][1] = f2tf(Ab[(m0 + g + 8) * (BKt + 4) + k0 + tg    ]);
                a[mi][2] = f2tf(Ab[(m0 + g    ) * (BKt + 4) + k0 + tg + 4]);
                a[mi][3] = f2tf(Ab[(m0 + g + 8) * (BKt + 4) + k0 + tg + 4]);
            }
#pragma unroll
            for (int ni = 0; ni < 4; ni++) {
                int n0 = wn * 32 + ni * 8;
                b[ni][0] = __float_as_uint(Bb[(k0 + tg    ) * (BN + 4) + n0 + g]);
                b[ni][1] = __float_as_uint(Bb[(k0 + tg + 4) * (BN + 4) + n0 + g]);
            }
#pragma unroll
            for (int mi = 0; mi < 2; mi++)
#pragma unroll
                for (int ni = 0; ni < 4; ni++)
                    mma_tf32(acc[mi][ni], a[mi], b[ni][0], b[ni][1]);
        }
        __syncthreads();   // all frag reads of buf done before it is refilled
    }

#pragma unroll
    for (int mi = 0; mi < 2; mi++) {
        int r0 = bm * BM + wm * 32 + mi * 16 + g;
#pragma unroll
        for (int ni = 0; ni < 4; ni++) {
            int c0 = bn * BN + wn * 32 + ni * 8 + tg * 2;
            float b0 = bias[c0], b1 = bias[c0 + 1];
            *(float2*)(C + (size_t)r0 * N + c0) =
                make_float2(acc[mi][ni][0] + b0, acc[mi][ni][1] + b1);
            *(float2*)(C + (size_t)(r0 + 8) * N + c0) =
                make_float2(acc[mi][ni][2] + b0, acc[mi][ni][3] + b1);
        }
    }
}

// ======================================================================
// Persistent recurrence kernel — UNCHANGED from R13 (passing, 847 us).
// ======================================================================
__device__ __forceinline__ float sigf(float x) { return 1.f / (1.f + expf(-x)); }

__device__ __forceinline__ void stage_w(const float* __restrict__ W, int nc0,
                                        unsigned* wHi, unsigned* wLo, int tid)
{
    for (int i = tid; i < 2048; i += 512) {
        int k = i >> 2, gate = i & 3;
        float4 w = *(const float4*)(W + (size_t)k * G4N_ + gate * 512 + nc0);
        unsigned h0 = f2tf(w.x), h1 = f2tf(w.y), h2 = f2tf(w.z), h3 = f2tf(w.w);
        unsigned l0 = __float_as_uint(w.x - __uint_as_float(h0));
        unsigned l1 = __float_as_uint(w.y - __uint_as_float(h1));
        unsigned l2 = __float_as_uint(w.z - __uint_as_float(h2));
        unsigned l3 = __float_as_uint(w.w - __uint_as_float(h3));
        *(uint4*)&wHi[k * WS_ + gate * 4] = make_uint4(h0, h1, h2, h3);
        *(uint4*)&wLo[k * WS_ + gate * 4] = make_uint4(l0, l1, l2, l3);
    }
}

__global__ __launch_bounds__(512, 1) void recurrence(
    const float* __restrict__ Wenc,   // lstm_rk [512][2048]
    const float* __restrict__ Wdec,   // [512][2048]
    const float* __restrict__ xk,     // [B*H][2048] (bias folded in)
    const float* __restrict__ lb,     // lstm_b [2048]
    float* __restrict__ preds)        // [B][P][N]
{
    extern __shared__ float sm[];
    unsigned* wHi = (unsigned*)sm;            // 12288 u32
    unsigned* wLo = (unsigned*)(sm + 12288);  // 12288 u32
    float* hsh    = sm + 24576;               // 32 x 516 = 16512 floats
    float* psumB  = sm + 41088;               // 2 x 4608 floats (step parity)

    const int tid  = threadIdx.x;
    const int lane = tid & 31;
    const int warp = tid >> 5;
    const int g    = lane >> 2;
    const int tg   = lane & 3;
    const int kg   = warp & 7;     // k-split group
    const int mi   = warp >> 3;    // row half
    const int m0   = mi * 16;
    const int nc0  = blockIdx.x * 4;

    const unsigned base = g_flags[blockIdx.x * 32];

    stage_w(Wenc, nc0, wHi, wLo, tid);

    const int b  = tid & 31;
    const int cu = tid >> 5;
    float lbr[4], cst = 0.f, pf[4];
    if (tid < 128) {
        d_h[0][(size_t)b * N_ + nc0 + cu] = 0.f;
#pragma unroll
        for (int q = 0; q < 4; q++) lbr[q] = lb[q * 512 + nc0 + cu];
        const float* xp = xk + ((size_t)b * H_) * G4N_ + nc0 + cu;
        pf[0] = __ldg(xp);
        pf[1] = __ldg(xp + 512);
        pf[2] = __ldg(xp + 1024);
        pf[3] = __ldg(xp + 1536);
    }
    __syncthreads();
    if (tid == 0)
        asm volatile("st.release.gpu.global.u32 [%0], %1;"
                     :: "l"(&g_flags[blockIdx.x * 32]), "r"(base + 1u) : "memory");

    const int jj = kg * 16 + (lane & 15);
    const unsigned* flagp = &g_flags[jj * 32];
    const int half = lane >> 4;
    const int r0s  = m0 + half * 8;
    const int scol = kg * 64 + (lane & 15) * 4;

    for (int s = 0; s < H_ + P_; s++) {
        if (s == H_) {
            stage_w(Wdec, nc0, wHi, wLo, tid);
            __syncthreads();
        }

        float pfn[4];
        if (tid < 128) {
            if (s + 1 < H_) {
                const float* xp = xk + ((size_t)b * H_ + (s + 1)) * G4N_ + nc0 + cu;
                pfn[0] = __ldg(xp);
                pfn[1] = __ldg(xp + 512);
                pfn[2] = __ldg(xp + 1024);
                pfn[3] = __ldg(xp + 1536);
            } else {
                pfn[0] = lbr[0]; pfn[1] = lbr[1]; pfn[2] = lbr[2]; pfn[3] = lbr[3];
            }
        }

        {
            const unsigned tgt = base + 1u + (unsigned)s;
            unsigned v;
            do {
                asm volatile("ld.acquire.gpu.global.u32 %0, [%1];"
                             : "=r"(v) : "l"(flagp) : "memory");
            } while ((int)(v - tgt) < 0);
        }
        {
            const float4* hb = (const float4*)d_h[s & 1];
            float4 hv[8];
#pragma unroll
            for (int r = 0; r < 8; r++)
                hv[r] = __ldcg(hb + (size_t)(r0s + r) * 128 + jj);
#pragma unroll
            for (int r = 0; r < 8; r++)
                *(float4*)&hsh[(r0s + r) * HS_ + scol] = hv[r];
        }
        __syncwarp();

        float ac0[2][4] = {{0.f,0.f,0.f,0.f},{0.f,0.f,0.f,0.f}};
        float ac1[2][4] = {{0.f,0.f,0.f,0.f},{0.f,0.f,0.f,0.f}};
#pragma unroll
        for (int f = 0; f < 8; f++) {
            const int k0 = kg * 64 + f * 8;
            const int c = f & 1;
            float a0 = hsh[(m0 + g    ) * HS_ + k0 + tg    ];
            float a1 = hsh[(m0 + g + 8) * HS_ + k0 + tg    ];
            float a2 = hsh[(m0 + g    ) * HS_ + k0 + tg + 4];
            float a3 = hsh[(m0 + g + 8) * HS_ + k0 + tg + 4];
            unsigned ahi[4], alo[4];
            ahi[0] = f2tf(a0); alo[0] = __float_as_uint(a0 - __uint_as_float(ahi[0]));
            ahi[1] = f2tf(a1); alo[1] = __float_as_uint(a1 - __uint_as_float(ahi[1]));
            ahi[2] = f2tf(a2); alo[2] = __float_as_uint(a2 - __uint_as_float(ahi[2]));
            ahi[3] = f2tf(a3); alo[3] = __float_as_uint(a3 - __uint_as_float(ahi[3]));
            unsigned bh0 = wHi[(k0 + tg    ) * WS_ + g];
            unsigned bh1 = wHi[(k0 + tg + 4) * WS_ + g];
            unsigned bh2 = wHi[(k0 + tg    ) * WS_ + 8 + g];
            unsigned bh3 = wHi[(k0 + tg + 4) * WS_ + 8 + g];
            unsigned bl0 = wLo[(k0 + tg    ) * WS_ + g];
            unsigned bl1 = wLo[(k0 + tg + 4) * WS_ + g];
            unsigned bl2 = wLo[(k0 + tg    ) * WS_ + 8 + g];
            unsigned bl3 = wLo[(k0 + tg + 4) * WS_ + 8 + g];
            mma_tf32(ac0[c], ahi, bh0, bh1);
            mma_tf32(ac0[c], alo, bh0, bh1);
            mma_tf32(ac0[c], ahi, bl0, bl1);
            mma_tf32(ac1[c], ahi, bh2, bh3);
            mma_tf32(ac1[c], alo, bh2, bh3);
            mma_tf32(ac1[c], ahi, bl2, bl3);
        }
        {
            float* psum = psumB + (s & 1) * 4608;
            const int c0 = tg * 2, r0 = m0 + g;
            psum[(kg * 16 + c0        ) * PS_ + r0    ] = ac0[0][0] + ac0[1][0];
            psum[(kg * 16 + c0 + 1    ) * PS_ + r0    ] = ac0[0][1] + ac0[1][1];
            psum[(kg * 16 + c0        ) * PS_ + r0 + 8] = ac0[0][2] + ac0[1][2];
            psum[(kg * 16 + c0 + 1    ) * PS_ + r0 + 8] = ac0[0][3] + ac0[1][3];
            psum[(kg * 16 + 8 + c0    ) * PS_ + r0    ] = ac1[0][0] + ac1[1][0];
            psum[(kg * 16 + 8 + c0 + 1) * PS_ + r0    ] = ac1[0][1] + ac1[1][1];
            psum[(kg * 16 + 8 + c0    ) * PS_ + r0 + 8] = ac1[0][2] + ac1[1][2];
            psum[(kg * 16 + 8 + c0 + 1) * PS_ + r0 + 8] = ac1[0][3] + ac1[1][3];
        }
        __syncthreads();

        if (tid < 128) {
            const float* psum = psumB + (s & 1) * 4608;
            float z[4];
#pragma unroll
            for (int q = 0; q < 4; q++) {
                const int n = q * 4 + cu;
                float accv = pf[q];
#pragma unroll
                for (int kk = 0; kk < 8; kk++)
                    accv += psum[(kk * 16 + n) * PS_ + b];
                z[q] = accv;
            }
            float ii = sigf(z[0]), ff = sigf(z[1]);
            float gg = tanhf(z[2]), oo = sigf(z[3]);
            cst = ff * cst + ii * gg;
            float hn = oo * tanhf(cst);
            d_h[(s + 1) & 1][(size_t)b * N_ + nc0 + cu] = hn;

            asm volatile("bar.sync 1, 128;" ::: "memory");
            if (tid == 0)
                asm volatile("st.release.gpu.global.u32 [%0], %1;"
                             :: "l"(&g_flags[blockIdx.x * 32]),
                                "r"(base + 2u + (unsigned)s) : "memory");

            if (s >= H_)
                preds[((size_t)b * P_ + (s - H_)) * N_ + nc0 + cu] = hn;

            pf[0] = pfn[0]; pf[1] = pfn[1]; pf[2] = pfn[2]; pf[3] = pfn[3];
        }
    }
}

// ======================================================================
// launch
// ======================================================================
extern "C" void kernel_launch(void* const* d_in, const int* in_sizes, int n_in,
                              void* d_out, int out_size)
{
    const float* x       = (const float*)d_in[0];
    const float* conv_w  = (const float*)d_in[1];
    const float* conv_b  = (const float*)d_in[2];
    const float* lstm_k  = (const float*)d_in[3];
    const float* lstm_rk = (const float*)d_in[4];
    const float* lstm_b  = (const float*)d_in[5];
    const float* dense_w = (const float*)d_in[6];
    const float* dense_b = (const float*)d_in[7];
    float* out = (float*)d_out;

    float *xr, *xk, *wdec, *preds, *cw, *lk, *dw;
    cudaGetSymbolAddress((void**)&xr,    d_xr);
    cudaGetSymbolAddress((void**)&xk,    d_xk);
    cudaGetSymbolAddress((void**)&wdec,  d_wdec);
    cudaGetSymbolAddress((void**)&preds, d_preds);
    cudaGetSymbolAddress((void**)&cw,    d_cw);
    cudaGetSymbolAddress((void**)&lk,    d_lk);
    cudaGetSymbolAddress((void**)&dw,    d_dw);

    const int GSMEM = NSTG * (ASZ + BSZ) * 4;  // 81408 B
    cudaFuncSetAttribute(gemm_pipe, cudaFuncAttributeMaxDynamicSharedMemorySize, GSMEM);
    const int RSMEM = (12288 + 12288 + 16512 + 2 * 4608) * 4;  // 201216 B
    cudaFuncSetAttribute(recurrence, cudaFuncAttributeMaxDynamicSharedMemorySize, RSMEM);

    // 0) weight prep: tf32 conversions + wdec = lstm_k + lstm_rk
    prep<<<(KIN_ * N_ + 255) / 256, 256>>>(conv_w, lstm_k, lstm_rk, dense_w);

    // 1) xr = reshape(x) @ conv_w + conv_b     [5376,4096]x[4096,512]
    {
        dim3 grid(N_ / BN, MR_ / BM);
        gemm_pipe<<<grid, 256, GSMEM>>>(x, cw, conv_b, xr, MR_, N_, KIN_);
    }
    // 2) xk = xr @ lstm_k + lstm_b             [5376,512]x[512,2048]
    {
        dim3 grid(G4N_ / BN, MR_ / BM);
        gemm_pipe<<<grid, 256, GSMEM>>>(xr, lk, lstm_b, xk, MR_, G4N_, N_);
    }
    // 3) encoder (168 steps) + decoder (24 steps), persistent dataflow
    recurrence<<<RGRID, 512, RSMEM>>>(lstm_rk, wdec, xk, lstm_b, preds);
    // 4) out = preds @ dense_w + dense_b       [768,512]x[512,512]
    {
        dim3 grid(N_ / BN, (B_ * P_) / BM);
        gemm_pipe<<<grid, 256, GSMEM>>>(preds, dw, dense_b, out, B_ * P_, N_, N_);
    }
}